// round 11
// baseline (speedup 1.0000x reference)
#include <cuda_runtime.h>
#include <math.h>

// ---------------------------------------------------------------------------
// Problem constants
//   x: (32, 256, 56, 56) f32 ; pos_embedding: (13,13) ; w_qkv: (256,768)
//   w_out: (256,256) ; b_out: (256)
//   out  = (32,256,56,56)  -> 25,690,112 floats
//   attn = (2048,8,49,49)  -> 39,337,984 floats   (concatenated after out)
// ---------------------------------------------------------------------------
#define BSZ    32
#define CDIM   256
#define HW     3136      // 56*56
#define PP     49
#define NWIN   64
#define HEADS  8
#define DH     32
#define MROWS  100352    // 32*64*49
#define NQKV   768
#define OUT_ELEMS 25690112

// Scratch (device globals -- allocation-free per harness rules)
__device__ float g_xw [(size_t)MROWS * CDIM];   // windowed x; reused as out-proj result
__device__ float g_qkv[(size_t)MROWS * NQKV];
__device__ float g_oi [(size_t)MROWS * CDIM];   // attention output (pre-projection)

// ---------------------------------------------------------------------------
// Kernel 1: roll(-3,-3) + window partition + channel transpose
//   g_xw[(b*3136 + tok)*256 + c] = x[b][c][yy][xx]
// ---------------------------------------------------------------------------
__global__ void window_gather_kernel(const float* __restrict__ x)
{
    __shared__ float tile[32][33];
    const int s0 = blockIdx.x * 32;
    const int c0 = blockIdx.y * 32;
    const int b  = blockIdx.z;

    tile[threadIdx.y][threadIdx.x] =
        x[(size_t)(b * CDIM + c0 + threadIdx.y) * HW + s0 + threadIdx.x];
    __syncthreads();

    const int s2 = s0 + threadIdx.y;
    const int yy = s2 / 56, xx = s2 - yy * 56;
    int i = yy + 53; if (i >= 56) i -= 56;     // (yy - 3) mod 56
    int j = xx + 53; if (j >= 56) j -= 56;
    const int tok = ((i / 7) * 8 + (j / 7)) * 49 + (i % 7) * 7 + (j % 7);

    g_xw[(size_t)(b * HW + tok) * CDIM + c0 + threadIdx.x] = tile[threadIdx.x][threadIdx.y];
}

// ---------------------------------------------------------------------------
// Kernel 5: inverse window partition + roll(+3,+3) back to (b,c,h,w)
// ---------------------------------------------------------------------------
__global__ void window_scatter_kernel(float* __restrict__ out)
{
    __shared__ float tile[32][33];
    const int s0 = blockIdx.x * 32;
    const int c0 = blockIdx.y * 32;
    const int b  = blockIdx.z;

    const int s2 = s0 + threadIdx.y;
    const int yy = s2 / 56, xx = s2 - yy * 56;
    int i = yy + 53; if (i >= 56) i -= 56;
    int j = xx + 53; if (j >= 56) j -= 56;
    const int tok = ((i / 7) * 8 + (j / 7)) * 49 + (i % 7) * 7 + (j % 7);

    tile[threadIdx.y][threadIdx.x] =
        g_xw[(size_t)(b * HW + tok) * CDIM + c0 + threadIdx.x];
    __syncthreads();

    out[(size_t)(b * CDIM + c0 + threadIdx.y) * HW + s0 + threadIdx.x] =
        tile[threadIdx.x][threadIdx.y];
}

// ---------------------------------------------------------------------------
// Kernels 2 & 4: fp32 SGEMM  C[M,N] = A[M,K] @ B[K,N] (+ bias)
//   128x128 block tile, BK=8, 8x8 per thread, 256 threads, float4 everywhere.
//   M,N multiples of 128; K multiple of 8 (checked by construction).
// ---------------------------------------------------------------------------
template<bool HAS_BIAS>
__global__ __launch_bounds__(256) void sgemm128(
    int K, int N,
    const float* __restrict__ A,
    const float* __restrict__ B,
    const float* __restrict__ bias,
    float* __restrict__ C)
{
    __shared__ float As[8][132];   // padded to kill store conflicts
    __shared__ float Bs[8][128];

    const int tid  = threadIdx.x;
    const int cRow = blockIdx.y;
    const int cCol = blockIdx.x;

    A += (size_t)cRow * 128 * K;
    B += cCol * 128;
    C += (size_t)cRow * 128 * N + cCol * 128;

    const int threadCol = tid & 15;          // 0..15
    const int threadRow = tid >> 4;          // 0..15
    const int innerRowA = tid >> 1;          // 0..127
    const int innerColA = (tid & 1) * 4;     // 0 or 4
    const int innerRowB = tid >> 5;          // 0..7
    const int innerColB = (tid & 31) * 4;    // 0..124

    float acc[8][8];
#pragma unroll
    for (int i = 0; i < 8; i++)
#pragma unroll
        for (int j = 0; j < 8; j++) acc[i][j] = 0.f;

    for (int kt = 0; kt < K; kt += 8) {
        float4 a4 = *(const float4*)(A + (size_t)innerRowA * K + kt + innerColA);
        As[innerColA + 0][innerRowA] = a4.x;
        As[innerColA + 1][innerRowA] = a4.y;
        As[innerColA + 2][innerRowA] = a4.z;
        As[innerColA + 3][innerRowA] = a4.w;
        *(float4*)(&Bs[innerRowB][innerColB]) =
            *(const float4*)(B + (size_t)(kt + innerRowB) * N + innerColB);
        __syncthreads();

#pragma unroll
        for (int k = 0; k < 8; k++) {
            float ra[8], rb[8];
#pragma unroll
            for (int i = 0; i < 8; i++) ra[i] = As[k][threadRow * 8 + i];
#pragma unroll
            for (int j = 0; j < 8; j++) rb[j] = Bs[k][threadCol * 8 + j];
#pragma unroll
            for (int i = 0; i < 8; i++)
#pragma unroll
                for (int j = 0; j < 8; j++)
                    acc[i][j] += ra[i] * rb[j];
        }
        __syncthreads();
    }

#pragma unroll
    for (int i = 0; i < 8; i++) {
        const int row = threadRow * 8 + i;
#pragma unroll
        for (int j = 0; j < 8; j += 4) {
            float4 v = make_float4(acc[i][j], acc[i][j+1], acc[i][j+2], acc[i][j+3]);
            if (HAS_BIAS) {
                const float* bp = bias + cCol * 128 + threadCol * 8 + j;
                v.x += bp[0]; v.y += bp[1]; v.z += bp[2]; v.w += bp[3];
            }
            *(float4*)(C + (size_t)row * N + threadCol * 8 + j) = v;
        }
    }
}

// ---------------------------------------------------------------------------
// Kernel 3: attention. One block per (b, window, head). 128 threads.
//   S = q@k^T * scale + bias + shift_mask ; softmax ; attn out ; O = P@v
// ---------------------------------------------------------------------------
__global__ __launch_bounds__(128) void attn_kernel(const float* __restrict__ pe,
                                                   float* __restrict__ attn_out)
{
    __shared__ float qs[64 * 33];
    __shared__ float ks[64 * 33];
    __shared__ float vs[64 * 33];
    __shared__ float S [64 * 49];   // rows 49..63 are scratch/garbage
    __shared__ float pes[169];

    const int bid = blockIdx.x;          // (bb*64 + wn)*8 + h
    const int h   = bid & 7;
    const int wn  = (bid >> 3) & 63;
    const int m0  = (bid >> 3) * PP;     // global token row base
    const int tid = threadIdx.x;

    for (int t = tid; t < 169; t += 128) pes[t] = pe[t];

    // load q,k,v slices for this head: 49 x 32 each
    for (int t = tid; t < PP * 8; t += 128) {
        const int i  = t >> 3;
        const int d4 = (t & 7) << 2;
        const float* base = g_qkv + (size_t)(m0 + i) * NQKV + h * DH + d4;
        float4 qa = *(const float4*)(base);
        float4 ka = *(const float4*)(base + 256);
        float4 va = *(const float4*)(base + 512);
        float* qp = qs + i * 33 + d4;
        qp[0] = qa.x; qp[1] = qa.y; qp[2] = qa.z; qp[3] = qa.w;
        float* kp = ks + i * 33 + d4;
        kp[0] = ka.x; kp[1] = ka.y; kp[2] = ka.z; kp[3] = ka.w;
        float* vp = vs + i * 33 + d4;
        vp[0] = va.x; vp[1] = va.y; vp[2] = va.z; vp[3] = va.w;
    }
    __syncthreads();

    const bool bottom = (wn >= 56);                 // ul mask: last n2 windows
    const bool right  = (wn == 55) || (wn == 63);   // lr mask: [-9::8]
    const float scale = 0.17677669529663687f;       // 32^-0.5
    const float NEG_INF = -INFINITY;

    // ---- phase 2: S[i][j] = scale * q_i . k_j + mask ----
    {
        const int ti = tid & 7;     // i = ti + 8u  (u<7)   covers 0..55
        const int tj = tid >> 3;    // j = tj + 16w (w<4)   covers 0..63
        float acc[7][4];
#pragma unroll
        for (int u = 0; u < 7; u++)
#pragma unroll
            for (int w = 0; w < 4; w++) acc[u][w] = 0.f;

#pragma unroll 4
        for (int d = 0; d < 32; d++) {
            float qv[7], kv[4];
#pragma unroll
            for (int u = 0; u < 7; u++) qv[u] = qs[(ti + 8 * u) * 33 + d];
#pragma unroll
            for (int w = 0; w < 4; w++) kv[w] = ks[(tj + 16 * w) * 33 + d];
#pragma unroll
            for (int u = 0; u < 7; u++)
#pragma unroll
                for (int w = 0; w < 4; w++)
                    acc[u][w] += qv[u] * kv[w];
        }

#pragma unroll
        for (int u = 0; u < 7; u++) {
            const int i = ti + 8 * u;
            if (i < PP) {
                const int iy = i / 7, ix = i - iy * 7;
#pragma unroll
                for (int w = 0; w < 4; w++) {
                    const int j = tj + 16 * w;
                    if (j < PP) {
                        const int jy = j / 7, jx = j - jy * 7;
                        float m = pes[(jy - iy + 6) * 13 + (jx - ix + 6)];
                        if (bottom && ((i >= 28) != (j >= 28))) m = NEG_INF;
                        if (right  && ((ix >= 4) != (jx >= 4))) m = NEG_INF;
                        S[i * 49 + j] = acc[u][w] * scale + m;
                    }
                }
            }
        }
    }
    __syncthreads();

    // ---- softmax per row (warp per row) + write attn output ----
    {
        const int warp = tid >> 5, lane = tid & 31;
        const size_t abase = (size_t)bid * (PP * PP);
        for (int r = warp; r < PP; r += 4) {
            float v0 = S[r * 49 + lane];
            float v1 = (lane + 32 < PP) ? S[r * 49 + lane + 32] : NEG_INF;
            float mx = fmaxf(v0, v1);
#pragma unroll
            for (int o = 16; o; o >>= 1) mx = fmaxf(mx, __shfl_xor_sync(0xffffffffu, mx, o));
            float e0 = __expf(v0 - mx);
            float e1 = (lane + 32 < PP) ? __expf(v1 - mx) : 0.f;
            float sm = e0 + e1;
#pragma unroll
            for (int o = 16; o; o >>= 1) sm += __shfl_xor_sync(0xffffffffu, sm, o);
            const float inv = 1.0f / sm;
            const float p0 = e0 * inv;
            S[r * 49 + lane] = p0;
            attn_out[abase + r * 49 + lane] = p0;
            if (lane + 32 < PP) {
                const float p1 = e1 * inv;
                S[r * 49 + lane + 32] = p1;
                attn_out[abase + r * 49 + lane + 32] = p1;
            }
        }
    }
    __syncthreads();

    // ---- phase 3: O[i][d] = sum_j P[i][j] * v[j][d] ----
    {
        const int td  = tid & 7;    // d = td + 8w  (w<4) covers 0..31
        const int ti3 = tid >> 3;   // i = ti3 + 16u (u<4) covers 0..63
        float acc[4][4];
#pragma unroll
        for (int u = 0; u < 4; u++)
#pragma unroll
            for (int w = 0; w < 4; w++) acc[u][w] = 0.f;

        for (int j = 0; j < PP; j++) {
            float pv[4], vv4[4];
#pragma unroll
            for (int u = 0; u < 4; u++) pv[u] = S[(ti3 + 16 * u) * 49 + j];
#pragma unroll
            for (int w = 0; w < 4; w++) vv4[w] = vs[j * 33 + td + 8 * w];
#pragma unroll
            for (int u = 0; u < 4; u++)
#pragma unroll
                for (int w = 0; w < 4; w++)
                    acc[u][w] += pv[u] * vv4[w];
        }

#pragma unroll
        for (int u = 0; u < 4; u++) {
            const int i = ti3 + 16 * u;
            if (i < PP) {
                float* op = g_oi + (size_t)(m0 + i) * CDIM + h * DH + td;
#pragma unroll
                for (int w = 0; w < 4; w++) op[8 * w] = acc[u][w];
            }
        }
    }
}

// ---------------------------------------------------------------------------
// Launch
// ---------------------------------------------------------------------------
extern "C" void kernel_launch(void* const* d_in, const int* in_sizes, int n_in,
                              void* d_out, int out_size)
{
    const float* x    = (const float*)d_in[0];
    const float* pe   = (const float*)d_in[1];
    const float* wqkv = (const float*)d_in[2];
    const float* wout = (const float*)d_in[3];
    const float* bout = (const float*)d_in[4];
    float* out = (float*)d_out;

    float *p_xw, *p_qkv, *p_oi;
    cudaGetSymbolAddress((void**)&p_xw,  g_xw);
    cudaGetSymbolAddress((void**)&p_qkv, g_qkv);
    cudaGetSymbolAddress((void**)&p_oi,  g_oi);

    // 1) roll + window partition + transpose to token-major
    window_gather_kernel<<<dim3(98, 8, 32), dim3(32, 32)>>>(x);

    // 2) qkv = xw @ w_qkv   (100352x256 @ 256x768)
    sgemm128<false><<<dim3(NQKV / 128, MROWS / 128), 256>>>(CDIM, NQKV, p_xw, wqkv, nullptr, p_qkv);

    // 3) attention per (b, window, head); writes attn output + g_oi
    attn_kernel<<<BSZ * NWIN * HEADS, 128>>>(pe, out + OUT_ELEMS);

    // 4) proj = oi @ w_out + b_out  (reuse g_xw as destination)
    sgemm128<true><<<dim3(CDIM / 128, MROWS / 128), 256>>>(CDIM, CDIM, p_oi, wout, bout, p_xw);

    // 5) inverse window partition + roll back
    window_scatter_kernel<<<dim3(98, 8, 32), dim3(32, 32)>>>(out);
}